// round 13
// baseline (speedup 1.0000x reference)
#include <cuda_runtime.h>
#include <math.h>
#include <stdint.h>

#define Bq 256
#define Nq 256
#define Dq 512
#define Cq 1024
#define NCHUNK 8
#define CH_ROWS (Nq / NCHUNK)   // 32 rows per fused block
#define NCCH 16                 // c-chunks in gemm (64 cols each)

// Scratch (device globals — no allocation allowed)
__device__ float  g_txtrn[Cq];                     // 1/||txt[c]||  (4 KB)
__device__ float  g_ppart[Bq * NCHUNK * Dq];       // partial weighted sums (4 MB)
__device__ float2 g_meta[Bq * NCHUNK];             // (m, den) per partial
__device__ float  g_pooled[Bq * Dq];               // pooled normalized tokens
__device__ float2 g_cmeta[Bq * NCCH];              // (max, sumexp) per (b, chunk)
__device__ float  g_xg[Bq];                        // logits[b][gt[b]] / tau

__device__ __forceinline__ float warp_sum1(float v) {
#pragma unroll
    for (int o = 16; o; o >>= 1) v += __shfl_xor_sync(0xffffffffu, v, o);
    return v;
}

__device__ __forceinline__ void warp_sum4(float& a, float& b, float& c, float& d) {
#pragma unroll
    for (int o = 16; o; o >>= 1) {
        a += __shfl_xor_sync(0xffffffffu, a, o);
        b += __shfl_xor_sync(0xffffffffu, b, o);
        c += __shfl_xor_sync(0xffffffffu, c, o);
        d += __shfl_xor_sync(0xffffffffu, d, o);
    }
}

__device__ __forceinline__ uint32_t f2tf32(float v) {
    uint32_t r;
    asm("cvt.rna.tf32.f32 %0, %1;" : "=r"(r) : "f"(v));
    return r;
}
__device__ __forceinline__ uint4 tf32x4(float4 v) {
    return make_uint4(f2tf32(v.x), f2tf32(v.y), f2tf32(v.z), f2tf32(v.w));
}
__device__ __forceinline__ uint4 tf32x4s(float4 v, float s) {
    return make_uint4(f2tf32(v.x * s), f2tf32(v.y * s), f2tf32(v.z * s), f2tf32(v.w * s));
}

// ---------------------------------------------------------------------------
// K1: reciprocal norms of text rows. One warp per row. grid = 128, block = 256.
// ---------------------------------------------------------------------------
__global__ void k_txtnorm(const float* __restrict__ txt) {
    int w = threadIdx.x >> 5, lane = threadIdx.x & 31;
    int row = blockIdx.x * 8 + w;
    const float4* src = (const float4*)(txt + (size_t)row * Dq);
    float ss = 0.f;
#pragma unroll
    for (int i = 0; i < 4; i++) {
        float4 v = src[lane + 32 * i];
        ss += v.x * v.x + v.y * v.y + v.z * v.z + v.w * v.w;
    }
    ss = warp_sum1(ss);
    if (lane == 0) g_txtrn[row] = 1.f / fmaxf(sqrtf(ss), 1e-12f);
}

// ---------------------------------------------------------------------------
// K2 (fused streaming pass): online softmax-weighted pooling, single read of
// toks (128 MB). grid = (NCHUNK, B) = 2048 blocks, block = 256.
// ---------------------------------------------------------------------------
__global__ void k_fused(const float* __restrict__ toks,
                        const float* __restrict__ txt,
                        const int* __restrict__ gt,
                        const float* __restrict__ p_log_attn_tau) {
    __shared__ float sm[8], sden[8];
    __shared__ float svec[8][Dq];

    int ch = blockIdx.x, b = blockIdx.y;
    int w = threadIdx.x >> 5, lane = threadIdx.x & 31;

    float at = expf(*p_log_attn_tau);
    at = fminf(fmaxf(at, 0.01f), 1.0f);
    float inv_at = 1.f / at;

    int g = __ldg(&gt[b]);
    const float4* xrow = (const float4*)(txt + (size_t)g * Dq);
    float4 xv[4];
    float ssx = 0.f;
#pragma unroll
    for (int i = 0; i < 4; i++) {
        xv[i] = xrow[lane + 32 * i];
        ssx += xv[i].x * xv[i].x + xv[i].y * xv[i].y + xv[i].z * xv[i].z + xv[i].w * xv[i].w;
    }
    ssx = warp_sum1(ssx);
    float scale_x = inv_at / fmaxf(sqrtf(ssx), 1e-12f);

    int row0 = b * Nq + ch * CH_ROWS + w * 4;
    const float4* base = (const float4*)(toks + (size_t)row0 * Dq);

    float m = -1e30f, den = 0.f;
    float4 acc[4];
#pragma unroll
    for (int i = 0; i < 4; i++) acc[i] = make_float4(0.f, 0.f, 0.f, 0.f);

    float4 t0[4], t1[4], u0[4], u1[4];
#pragma unroll
    for (int i = 0; i < 4; i++) t0[i] = __ldcs(&base[lane + 32 * i]);
#pragma unroll
    for (int i = 0; i < 4; i++) t1[i] = __ldcs(&base[128 + lane + 32 * i]);

#pragma unroll
    for (int rp = 0; rp < 2; rp++) {
        if (rp == 0) {
#pragma unroll
            for (int i = 0; i < 4; i++) u0[i] = __ldcs(&base[256 + lane + 32 * i]);
#pragma unroll
            for (int i = 0; i < 4; i++) u1[i] = __ldcs(&base[384 + lane + 32 * i]);
        }
        float ss0 = 0.f, dp0 = 0.f, ss1 = 0.f, dp1 = 0.f;
#pragma unroll
        for (int i = 0; i < 4; i++) {
            ss0 += t0[i].x * t0[i].x + t0[i].y * t0[i].y + t0[i].z * t0[i].z + t0[i].w * t0[i].w;
            dp0 += t0[i].x * xv[i].x + t0[i].y * xv[i].y + t0[i].z * xv[i].z + t0[i].w * xv[i].w;
            ss1 += t1[i].x * t1[i].x + t1[i].y * t1[i].y + t1[i].z * t1[i].z + t1[i].w * t1[i].w;
            dp1 += t1[i].x * xv[i].x + t1[i].y * xv[i].y + t1[i].z * xv[i].z + t1[i].w * xv[i].w;
        }
        warp_sum4(ss0, dp0, ss1, dp1);

        float rn0 = 1.f / fmaxf(sqrtf(ss0), 1e-12f);
        float rn1 = 1.f / fmaxf(sqrtf(ss1), 1e-12f);
        float s0 = dp0 * rn0 * scale_x;
        float s1 = dp1 * rn1 * scale_x;
        float mnew = fmaxf(m, fmaxf(s0, s1));
        float scale = expf(m - mnew);
        float e0 = expf(s0 - mnew);
        float e1 = expf(s1 - mnew);
        den = den * scale + e0 + e1;
        float c0 = e0 * rn0, c1 = e1 * rn1;
#pragma unroll
        for (int i = 0; i < 4; i++) {
            acc[i].x = fmaf(c1, t1[i].x, fmaf(c0, t0[i].x, acc[i].x * scale));
            acc[i].y = fmaf(c1, t1[i].y, fmaf(c0, t0[i].y, acc[i].y * scale));
            acc[i].z = fmaf(c1, t1[i].z, fmaf(c0, t0[i].z, acc[i].z * scale));
            acc[i].w = fmaf(c1, t1[i].w, fmaf(c0, t0[i].w, acc[i].w * scale));
        }
        m = mnew;
        if (rp == 0) {
#pragma unroll
            for (int i = 0; i < 4; i++) { t0[i] = u0[i]; t1[i] = u1[i]; }
        }
    }

    if (lane == 0) { sm[w] = m; sden[w] = den; }
    float4* sv = (float4*)svec[w];
#pragma unroll
    for (int i = 0; i < 4; i++) sv[lane + 32 * i] = acc[i];
    __syncthreads();

    float M = sm[0];
#pragma unroll
    for (int i = 1; i < 8; i++) M = fmaxf(M, sm[i]);
    float wsc[8];
    float denb = 0.f;
#pragma unroll
    for (int i = 0; i < 8; i++) { wsc[i] = expf(sm[i] - M); denb = fmaf(wsc[i], sden[i], denb); }

    int tid = threadIdx.x;
    float* outp = g_ppart + (size_t)(b * NCHUNK + ch) * Dq;
#pragma unroll
    for (int rep = 0; rep < 2; rep++) {
        int d = tid + rep * 256;
        float v = 0.f;
#pragma unroll
        for (int i = 0; i < 8; i++) v = fmaf(wsc[i], svec[i][d], v);
        outp[d] = v;
    }
    if (tid == 0) g_meta[b * NCHUNK + ch] = make_float2(M, denb);
}

// ---------------------------------------------------------------------------
// K3: combine NCHUNK partials per b -> pooled[b,:]. grid = B, block = 128.
// ---------------------------------------------------------------------------
__global__ void k_combine() {
    int b = blockIdx.x, tid = threadIdx.x;
    float2 mt[NCHUNK];
#pragma unroll
    for (int i = 0; i < NCHUNK; i++) mt[i] = g_meta[b * NCHUNK + i];
    float M = mt[0].x;
#pragma unroll
    for (int i = 1; i < NCHUNK; i++) M = fmaxf(M, mt[i].x);
    float den = 0.f;
    float sc[NCHUNK];
#pragma unroll
    for (int i = 0; i < NCHUNK; i++) { sc[i] = expf(mt[i].x - M); den = fmaf(sc[i], mt[i].y, den); }
    float inv_den = 1.f / den;

    const float4* part = (const float4*)(g_ppart + (size_t)b * NCHUNK * Dq);
    float4 acc = make_float4(0.f, 0.f, 0.f, 0.f);
#pragma unroll
    for (int i = 0; i < NCHUNK; i++) {
        float4 p = part[(size_t)i * (Dq / 4) + tid];
        acc.x = fmaf(sc[i], p.x, acc.x);
        acc.y = fmaf(sc[i], p.y, acc.y);
        acc.z = fmaf(sc[i], p.z, acc.z);
        acc.w = fmaf(sc[i], p.w, acc.w);
    }
    acc.x *= inv_den; acc.y *= inv_den; acc.z *= inv_den; acc.w *= inv_den;
    ((float4*)(g_pooled + (size_t)b * Dq))[tid] = acc;
}

// ---------------------------------------------------------------------------
// K4: fused GEMM + chunk-softmax-stats. Full K=512 per CTA (16 prefetch-
// pipelined stages of 32). Tile 32b x 64c, block = 256: 8 warps (2 M x 4 N),
// each warp m16n16. grid = (NCCH, B/32) = (16, 8) = 128 CTAs.
// Epilogue: per-(row, chunk) online-softmax stats (max, sumexp) -> g_cmeta,
// and the gt-column logit -> g_xg. No logits array is ever materialized.
// ---------------------------------------------------------------------------
__global__ void __launch_bounds__(256) k_gemm_ce(const float* __restrict__ txt,
                                                 const float* __restrict__ p_log_tau,
                                                 const int* __restrict__ gt) {
    __shared__ __align__(16) uint32_t As[32][36];
    __shared__ __align__(16) uint32_t Bs[64][36];
    __shared__ float rmax[4][32], rsum[4][32];
    __shared__ int sgt[32];

    int tid = threadIdx.x;
    int c0 = blockIdx.x * 64;
    int b0 = blockIdx.y * 32;

    if (tid < 32) sgt[tid] = gt[b0 + tid];

    float tau = expf(*p_log_tau);
    tau = fminf(fmaxf(tau, 0.01f), 1.0f);
    float inv = 1.f / tau;

    int warp = tid >> 5, lane = tid & 31;
    int warpM = warp & 1;          // 2 m-tiles of 16 rows
    int warpN = warp >> 1;         // 4 n-groups of 16 cols
    int qg = lane >> 2, qt = lane & 3;

    int r = tid >> 3;              // 0..31
    int cc = (tid & 7) * 4;        // 0..28
    const float* pA = &g_pooled[(size_t)(b0 + r) * Dq + cc];
    const float* pB = &txt[(size_t)(c0 + r) * Dq + cc];
    float rnb0 = g_txtrn[c0 + r];
    float rnb1 = g_txtrn[c0 + r + 32];

    // stage-0 loads
    float4 a0 = *(const float4*)pA;
    float4 v0 = *(const float4*)pB;
    float4 v1 = *(const float4*)(pB + 32 * Dq);

    float d[2][4];
#pragma unroll
    for (int nt = 0; nt < 2; nt++)
#pragma unroll
        for (int f = 0; f < 4; f++) d[nt][f] = 0.f;

#pragma unroll 1
    for (int stage = 0; stage < 16; stage++) {
        *(uint4*)&As[r][cc]      = tf32x4(a0);
        *(uint4*)&Bs[r][cc]      = tf32x4s(v0, rnb0);
        *(uint4*)&Bs[r + 32][cc] = tf32x4s(v1, rnb1);
        __syncthreads();

        if (stage < 15) {   // prefetch next 32-k slab
            int o = (stage + 1) * 32;
            a0 = *(const float4*)(pA + o);
            v0 = *(const float4*)(pB + o);
            v1 = *(const float4*)(pB + 32 * Dq + o);
        }

#pragma unroll
        for (int ks = 0; ks < 4; ks++) {
            int k = ks * 8;
            int row = warpM * 16 + qg;
            uint32_t af0 = As[row][k + qt];
            uint32_t af1 = As[row + 8][k + qt];
            uint32_t af2 = As[row][k + qt + 4];
            uint32_t af3 = As[row + 8][k + qt + 4];
#pragma unroll
            for (int nt = 0; nt < 2; nt++) {
                int n = warpN * 16 + nt * 8 + qg;
                uint32_t bf0 = Bs[n][k + qt];
                uint32_t bf1 = Bs[n][k + qt + 4];
                asm volatile(
                    "mma.sync.aligned.m16n8k8.row.col.f32.tf32.tf32.f32 "
                    "{%0,%1,%2,%3}, {%4,%5,%6,%7}, {%8,%9}, {%0,%1,%2,%3};"
                    : "+f"(d[nt][0]), "+f"(d[nt][1]), "+f"(d[nt][2]), "+f"(d[nt][3])
                    : "r"(af0), "r"(af1), "r"(af2), "r"(af3), "r"(bf0), "r"(bf1));
            }
        }
        __syncthreads();
    }

    // ---- epilogue: tau-scale, per-row chunk stats, gt extraction ----
    int ra = warpM * 16 + qg;          // first row this thread covers
    float va[4] = {d[0][0] * inv, d[0][1] * inv, d[1][0] * inv, d[1][1] * inv};
    float vb[4] = {d[0][2] * inv, d[0][3] * inv, d[1][2] * inv, d[1][3] * inv};

    // gt-column extraction (exactly one thread across all CTAs matches per b)
    int g0 = sgt[ra], g1 = sgt[ra + 8];
#pragma unroll
    for (int nt = 0; nt < 2; nt++)
#pragma unroll
        for (int j = 0; j < 2; j++) {
            int col = c0 + warpN * 16 + nt * 8 + 2 * qt + j;
            if (col == g0) g_xg[b0 + ra] = va[nt * 2 + j];
            if (col == g1) g_xg[b0 + ra + 8] = vb[nt * 2 + j];
        }

    // quad-reduce max then sumexp for each of the two rows
    float ma = fmaxf(fmaxf(va[0], va[1]), fmaxf(va[2], va[3]));
    float mb = fmaxf(fmaxf(vb[0], vb[1]), fmaxf(vb[2], vb[3]));
    ma = fmaxf(ma, __shfl_xor_sync(0xffffffffu, ma, 1));
    ma = fmaxf(ma, __shfl_xor_sync(0xffffffffu, ma, 2));
    mb = fmaxf(mb, __shfl_xor_sync(0xffffffffu, mb, 1));
    mb = fmaxf(mb, __shfl_xor_sync(0xffffffffu, mb, 2));
    float sa = expf(va[0] - ma) + expf(va[1] - ma) + expf(va[2] - ma) + expf(va[3] - ma);
    float sb = expf(vb[0] - mb) + expf(vb[1] - mb) + expf(vb[2] - mb) + expf(vb[3] - mb);
    sa += __shfl_xor_sync(0xffffffffu, sa, 1);
    sa += __shfl_xor_sync(0xffffffffu, sa, 2);
    sb += __shfl_xor_sync(0xffffffffu, sb, 1);
    sb += __shfl_xor_sync(0xffffffffu, sb, 2);
    if (qt == 0) {
        rmax[warpN][ra] = ma;     rsum[warpN][ra] = sa;
        rmax[warpN][ra + 8] = mb; rsum[warpN][ra + 8] = sb;
    }
    __syncthreads();

    if (tid < 32) {
        float M = fmaxf(fmaxf(rmax[0][tid], rmax[1][tid]),
                        fmaxf(rmax[2][tid], rmax[3][tid]));
        float S = expf(rmax[0][tid] - M) * rsum[0][tid]
                + expf(rmax[1][tid] - M) * rsum[1][tid]
                + expf(rmax[2][tid] - M) * rsum[2][tid]
                + expf(rmax[3][tid] - M) * rsum[3][tid];
        g_cmeta[(size_t)(b0 + tid) * NCCH + blockIdx.x] = make_float2(M, S);
    }
}

// ---------------------------------------------------------------------------
// K5: final combine — logsumexp over NCCH chunk stats, nll, mean.
// 1 block, 256 threads (one per b).
// ---------------------------------------------------------------------------
__global__ void k_ce2(float* __restrict__ out) {
    __shared__ float red[256];
    int b = threadIdx.x;
    float2 mt[NCCH];
#pragma unroll
    for (int i = 0; i < NCCH; i++) mt[i] = g_cmeta[(size_t)b * NCCH + i];
    float M = mt[0].x;
#pragma unroll
    for (int i = 1; i < NCCH; i++) M = fmaxf(M, mt[i].x);
    float den = 0.f;
#pragma unroll
    for (int i = 0; i < NCCH; i++) den = fmaf(expf(mt[i].x - M), mt[i].y, den);
    float nll = logf(den) + M - g_xg[b];

    red[b] = nll;
    __syncthreads();
#pragma unroll
    for (int s = 128; s; s >>= 1) {
        if (b < s) red[b] += red[b + s];
        __syncthreads();
    }
    if (b == 0) out[0] = red[0] * (1.0f / (float)Bq);
}

// ---------------------------------------------------------------------------
extern "C" void kernel_launch(void* const* d_in, const int* in_sizes, int n_in,
                              void* d_out, int out_size) {
    const float* toks         = (const float*)d_in[0];  // [B,N,D] f32
    const float* txt          = (const float*)d_in[1];  // [C,D]   f32
    const float* log_tau      = (const float*)d_in[2];  // scalar
    const float* log_attn_tau = (const float*)d_in[3];  // scalar
    const int*   gt           = (const int*)d_in[4];    // [B] int32
    float* out = (float*)d_out;

    k_txtnorm<<<Cq / 8, 256>>>(txt);
    dim3 gf(NCHUNK, Bq);
    k_fused<<<gf, 256>>>(toks, txt, gt, log_attn_tau);
    k_combine<<<Bq, 128>>>();
    dim3 gg(NCCH, Bq / 32);
    k_gemm_ce<<<gg, 256>>>(txt, log_tau, gt);
    k_ce2<<<1, 256>>>(out);
}

// round 14
// speedup vs baseline: 1.0712x; 1.0712x over previous
#include <cuda_runtime.h>
#include <math.h>
#include <stdint.h>

#define Bq 256
#define Nq 256
#define Dq 512
#define Cq 1024
#define NCHUNK 8
#define CH_ROWS (Nq / NCHUNK)   // 32 rows per fused block
#define NCCH 16                 // c-chunks in gemm (64 cols each)

// Scratch (device globals — no allocation allowed)
__device__ float  g_ppart[Bq * NCHUNK * Dq];       // partial weighted sums (4 MB)
__device__ float2 g_meta[Bq * NCHUNK];             // (m, den) per partial
__device__ float  g_pooled[Bq * Dq];               // pooled normalized tokens
__device__ float2 g_cmeta[Bq * NCCH];              // (max, sumexp) per (b, chunk)
__device__ float  g_xg[Bq];                        // logits[b][gt[b]] / tau

__device__ __forceinline__ float warp_sum1(float v) {
#pragma unroll
    for (int o = 16; o; o >>= 1) v += __shfl_xor_sync(0xffffffffu, v, o);
    return v;
}

__device__ __forceinline__ void warp_sum4(float& a, float& b, float& c, float& d) {
#pragma unroll
    for (int o = 16; o; o >>= 1) {
        a += __shfl_xor_sync(0xffffffffu, a, o);
        b += __shfl_xor_sync(0xffffffffu, b, o);
        c += __shfl_xor_sync(0xffffffffu, c, o);
        d += __shfl_xor_sync(0xffffffffu, d, o);
    }
}

__device__ __forceinline__ uint32_t f2tf32(float v) {
    uint32_t r;
    asm("cvt.rna.tf32.f32 %0, %1;" : "=r"(r) : "f"(v));
    return r;
}
__device__ __forceinline__ uint4 tf32x4(float4 v) {
    return make_uint4(f2tf32(v.x), f2tf32(v.y), f2tf32(v.z), f2tf32(v.w));
}

// ---------------------------------------------------------------------------
// K1 (fused streaming pass): online softmax-weighted pooling, single read of
// toks (128 MB). Self-normalizes its text row.
// grid = (NCHUNK, B) = 2048 blocks, block = 256 (8 warps x 4 rows).
// ---------------------------------------------------------------------------
__global__ void k_fused(const float* __restrict__ toks,
                        const float* __restrict__ txt,
                        const int* __restrict__ gt,
                        const float* __restrict__ p_log_attn_tau) {
    __shared__ float sm[8], sden[8];
    __shared__ float svec[8][Dq];

    int ch = blockIdx.x, b = blockIdx.y;
    int w = threadIdx.x >> 5, lane = threadIdx.x & 31;

    float at = expf(*p_log_attn_tau);
    at = fminf(fmaxf(at, 0.01f), 1.0f);
    float inv_at = 1.f / at;

    int g = __ldg(&gt[b]);
    const float4* xrow = (const float4*)(txt + (size_t)g * Dq);
    float4 xv[4];
    float ssx = 0.f;
#pragma unroll
    for (int i = 0; i < 4; i++) {
        xv[i] = xrow[lane + 32 * i];
        ssx += xv[i].x * xv[i].x + xv[i].y * xv[i].y + xv[i].z * xv[i].z + xv[i].w * xv[i].w;
    }
    ssx = warp_sum1(ssx);
    float scale_x = inv_at / fmaxf(sqrtf(ssx), 1e-12f);

    int row0 = b * Nq + ch * CH_ROWS + w * 4;
    const float4* base = (const float4*)(toks + (size_t)row0 * Dq);

    float m = -1e30f, den = 0.f;
    float4 acc[4];
#pragma unroll
    for (int i = 0; i < 4; i++) acc[i] = make_float4(0.f, 0.f, 0.f, 0.f);

    float4 t0[4], t1[4], u0[4], u1[4];
#pragma unroll
    for (int i = 0; i < 4; i++) t0[i] = __ldcs(&base[lane + 32 * i]);
#pragma unroll
    for (int i = 0; i < 4; i++) t1[i] = __ldcs(&base[128 + lane + 32 * i]);

#pragma unroll
    for (int rp = 0; rp < 2; rp++) {
        if (rp == 0) {
#pragma unroll
            for (int i = 0; i < 4; i++) u0[i] = __ldcs(&base[256 + lane + 32 * i]);
#pragma unroll
            for (int i = 0; i < 4; i++) u1[i] = __ldcs(&base[384 + lane + 32 * i]);
        }
        float ss0 = 0.f, dp0 = 0.f, ss1 = 0.f, dp1 = 0.f;
#pragma unroll
        for (int i = 0; i < 4; i++) {
            ss0 += t0[i].x * t0[i].x + t0[i].y * t0[i].y + t0[i].z * t0[i].z + t0[i].w * t0[i].w;
            dp0 += t0[i].x * xv[i].x + t0[i].y * xv[i].y + t0[i].z * xv[i].z + t0[i].w * xv[i].w;
            ss1 += t1[i].x * t1[i].x + t1[i].y * t1[i].y + t1[i].z * t1[i].z + t1[i].w * t1[i].w;
            dp1 += t1[i].x * xv[i].x + t1[i].y * xv[i].y + t1[i].z * xv[i].z + t1[i].w * xv[i].w;
        }
        warp_sum4(ss0, dp0, ss1, dp1);

        float rn0 = 1.f / fmaxf(sqrtf(ss0), 1e-12f);
        float rn1 = 1.f / fmaxf(sqrtf(ss1), 1e-12f);
        float s0 = dp0 * rn0 * scale_x;
        float s1 = dp1 * rn1 * scale_x;
        float mnew = fmaxf(m, fmaxf(s0, s1));
        float scale = expf(m - mnew);
        float e0 = expf(s0 - mnew);
        float e1 = expf(s1 - mnew);
        den = den * scale + e0 + e1;
        float c0 = e0 * rn0, c1 = e1 * rn1;
#pragma unroll
        for (int i = 0; i < 4; i++) {
            acc[i].x = fmaf(c1, t1[i].x, fmaf(c0, t0[i].x, acc[i].x * scale));
            acc[i].y = fmaf(c1, t1[i].y, fmaf(c0, t0[i].y, acc[i].y * scale));
            acc[i].z = fmaf(c1, t1[i].z, fmaf(c0, t0[i].z, acc[i].z * scale));
            acc[i].w = fmaf(c1, t1[i].w, fmaf(c0, t0[i].w, acc[i].w * scale));
        }
        m = mnew;
        if (rp == 0) {
#pragma unroll
            for (int i = 0; i < 4; i++) { t0[i] = u0[i]; t1[i] = u1[i]; }
        }
    }

    if (lane == 0) { sm[w] = m; sden[w] = den; }
    float4* sv = (float4*)svec[w];
#pragma unroll
    for (int i = 0; i < 4; i++) sv[lane + 32 * i] = acc[i];
    __syncthreads();

    float M = sm[0];
#pragma unroll
    for (int i = 1; i < 8; i++) M = fmaxf(M, sm[i]);
    float wsc[8];
    float denb = 0.f;
#pragma unroll
    for (int i = 0; i < 8; i++) { wsc[i] = expf(sm[i] - M); denb = fmaf(wsc[i], sden[i], denb); }

    int tid = threadIdx.x;
    float* outp = g_ppart + (size_t)(b * NCHUNK + ch) * Dq;
#pragma unroll
    for (int rep = 0; rep < 2; rep++) {
        int d = tid + rep * 256;
        float v = 0.f;
#pragma unroll
        for (int i = 0; i < 8; i++) v = fmaf(wsc[i], svec[i][d], v);
        outp[d] = v;
    }
    if (tid == 0) g_meta[b * NCHUNK + ch] = make_float2(M, denb);
}

// ---------------------------------------------------------------------------
// K2: combine NCHUNK partials per b -> pooled[b,:]. grid = B, block = 128.
// ---------------------------------------------------------------------------
__global__ void k_combine() {
    int b = blockIdx.x, tid = threadIdx.x;
    float2 mt[NCHUNK];
#pragma unroll
    for (int i = 0; i < NCHUNK; i++) mt[i] = g_meta[b * NCHUNK + i];
    float M = mt[0].x;
#pragma unroll
    for (int i = 1; i < NCHUNK; i++) M = fmaxf(M, mt[i].x);
    float den = 0.f;
    float sc[NCHUNK];
#pragma unroll
    for (int i = 0; i < NCHUNK; i++) { sc[i] = expf(mt[i].x - M); den = fmaf(sc[i], mt[i].y, den); }
    float inv_den = 1.f / den;

    const float4* part = (const float4*)(g_ppart + (size_t)b * NCHUNK * Dq);
    float4 acc = make_float4(0.f, 0.f, 0.f, 0.f);
#pragma unroll
    for (int i = 0; i < NCHUNK; i++) {
        float4 p = part[(size_t)i * (Dq / 4) + tid];
        acc.x = fmaf(sc[i], p.x, acc.x);
        acc.y = fmaf(sc[i], p.y, acc.y);
        acc.z = fmaf(sc[i], p.z, acc.z);
        acc.w = fmaf(sc[i], p.w, acc.w);
    }
    acc.x *= inv_den; acc.y *= inv_den; acc.z *= inv_den; acc.w *= inv_den;
    ((float4*)(g_pooled + (size_t)b * Dq))[tid] = acc;
}

// ---------------------------------------------------------------------------
// K3: fused GEMM + chunk-softmax-stats, smem double-buffered, full K=512
// (16 stages of 32). Tile 32b x 64c, block 256 (8 warps = 2M x 4N, warp
// m16n16). grid = (NCCH, B/32) = (16, 8) = 128 CTAs.
// Text read RAW; per-column 1/||txt_c|| computed in-CTA from the loads and
// applied in the epilogue (rn_c scales a whole output column).
// One __syncthreads per stage: STS(buf s) -> sync -> LDG(s+1) -> MMA(buf s).
// ---------------------------------------------------------------------------
__global__ void __launch_bounds__(256) k_gemm_ce(const float* __restrict__ txt,
                                                 const float* __restrict__ p_log_tau,
                                                 const int* __restrict__ gt) {
    __shared__ __align__(16) uint32_t As[2][32][36];
    __shared__ __align__(16) uint32_t Bs[2][64][36];
    __shared__ float rmax[4][32], rsum[4][32];
    __shared__ float srn[64];
    __shared__ int sgt[32];

    int tid = threadIdx.x;
    int c0 = blockIdx.x * 64;
    int b0 = blockIdx.y * 32;

    if (tid < 32) sgt[tid] = gt[b0 + tid];

    float tau = expf(*p_log_tau);
    tau = fminf(fmaxf(tau, 0.01f), 1.0f);
    float inv = 1.f / tau;

    int warp = tid >> 5, lane = tid & 31;
    int warpM = warp & 1;          // 2 m-tiles of 16 rows
    int warpN = warp >> 1;         // 4 n-groups of 16 cols
    int qg = lane >> 2, qt = lane & 3;

    int r = tid >> 3;              // 0..31
    int cc = (tid & 7) * 4;        // 0..28
    const float* pA = &g_pooled[(size_t)(b0 + r) * Dq + cc];
    const float* pB0 = &txt[(size_t)(c0 + r) * Dq + cc];
    const float* pB1 = &txt[(size_t)(c0 + r + 32) * Dq + cc];

    float ssb0 = 0.f, ssb1 = 0.f;  // partial sum-squares of txt rows r, r+32

    // prologue: stage-0 loads
    float4 a0 = *(const float4*)pA;
    float4 v0 = *(const float4*)pB0;
    float4 v1 = *(const float4*)pB1;

    float d[2][4];
#pragma unroll
    for (int nt = 0; nt < 2; nt++)
#pragma unroll
        for (int f = 0; f < 4; f++) d[nt][f] = 0.f;

#pragma unroll 1
    for (int stage = 0; stage < 16; stage++) {
        int buf = stage & 1;
        *(uint4*)&As[buf][r][cc]      = tf32x4(a0);
        *(uint4*)&Bs[buf][r][cc]      = tf32x4(v0);
        *(uint4*)&Bs[buf][r + 32][cc] = tf32x4(v1);
        ssb0 += v0.x * v0.x + v0.y * v0.y + v0.z * v0.z + v0.w * v0.w;
        ssb1 += v1.x * v1.x + v1.y * v1.y + v1.z * v1.z + v1.w * v1.w;
        __syncthreads();

        if (stage < 15) {   // prefetch next 32-k slab (hidden under MMA below)
            int o = (stage + 1) * 32;
            a0 = *(const float4*)(pA + o);
            v0 = *(const float4*)(pB0 + o);
            v1 = *(const float4*)(pB1 + o);
        }

#pragma unroll
        for (int ks = 0; ks < 4; ks++) {
            int k = ks * 8;
            int row = warpM * 16 + qg;
            uint32_t af0 = As[buf][row][k + qt];
            uint32_t af1 = As[buf][row + 8][k + qt];
            uint32_t af2 = As[buf][row][k + qt + 4];
            uint32_t af3 = As[buf][row + 8][k + qt + 4];
#pragma unroll
            for (int nt = 0; nt < 2; nt++) {
                int n = warpN * 16 + nt * 8 + qg;
                uint32_t bf0 = Bs[buf][n][k + qt];
                uint32_t bf1 = Bs[buf][n][k + qt + 4];
                asm volatile(
                    "mma.sync.aligned.m16n8k8.row.col.f32.tf32.tf32.f32 "
                    "{%0,%1,%2,%3}, {%4,%5,%6,%7}, {%8,%9}, {%0,%1,%2,%3};"
                    : "+f"(d[nt][0]), "+f"(d[nt][1]), "+f"(d[nt][2]), "+f"(d[nt][3])
                    : "r"(af0), "r"(af1), "r"(af2), "r"(af3), "r"(bf0), "r"(bf1));
            }
        }
    }

    // ---- per-column reciprocal norms: reduce ssb over the 8-lane group ----
#pragma unroll
    for (int o = 1; o < 8; o <<= 1) {
        ssb0 += __shfl_xor_sync(0xffffffffu, ssb0, o);
        ssb1 += __shfl_xor_sync(0xffffffffu, ssb1, o);
    }
    if ((tid & 7) == 0) {
        srn[r]      = 1.f / fmaxf(sqrtf(ssb0), 1e-12f);
        srn[r + 32] = 1.f / fmaxf(sqrtf(ssb1), 1e-12f);
    }
    __syncthreads();

    // ---- epilogue: scale by rn_c * inv_tau, chunk stats, gt extraction ----
    int ra = warpM * 16 + qg;
    float va[4], vb[4];
#pragma unroll
    for (int nt = 0; nt < 2; nt++)
#pragma unroll
        for (int j = 0; j < 2; j++) {
            int ci = warpN * 16 + nt * 8 + 2 * qt + j;
            float s = srn[ci] * inv;
            va[nt * 2 + j] = d[nt][j] * s;
            vb[nt * 2 + j] = d[nt][j + 2] * s;
        }

    int g0 = sgt[ra], g1 = sgt[ra + 8];
#pragma unroll
    for (int nt = 0; nt < 2; nt++)
#pragma unroll
        for (int j = 0; j < 2; j++) {
            int col = c0 + warpN * 16 + nt * 8 + 2 * qt + j;
            if (col == g0) g_xg[b0 + ra] = va[nt * 2 + j];
            if (col == g1) g_xg[b0 + ra + 8] = vb[nt * 2 + j];
        }

    float ma = fmaxf(fmaxf(va[0], va[1]), fmaxf(va[2], va[3]));
    float mb = fmaxf(fmaxf(vb[0], vb[1]), fmaxf(vb[2], vb[3]));
    ma = fmaxf(ma, __shfl_xor_sync(0xffffffffu, ma, 1));
    ma = fmaxf(ma, __shfl_xor_sync(0xffffffffu, ma, 2));
    mb = fmaxf(mb, __shfl_xor_sync(0xffffffffu, mb, 1));
    mb = fmaxf(mb, __shfl_xor_sync(0xffffffffu, mb, 2));
    float sa = expf(va[0] - ma) + expf(va[1] - ma) + expf(va[2] - ma) + expf(va[3] - ma);
    float sb = expf(vb[0] - mb) + expf(vb[1] - mb) + expf(vb[2] - mb) + expf(vb[3] - mb);
    sa += __shfl_xor_sync(0xffffffffu, sa, 1);
    sa += __shfl_xor_sync(0xffffffffu, sa, 2);
    sb += __shfl_xor_sync(0xffffffffu, sb, 1);
    sb += __shfl_xor_sync(0xffffffffu, sb, 2);
    if (qt == 0) {
        rmax[warpN][ra] = ma;     rsum[warpN][ra] = sa;
        rmax[warpN][ra + 8] = mb; rsum[warpN][ra + 8] = sb;
    }
    __syncthreads();

    if (tid < 32) {
        float M = fmaxf(fmaxf(rmax[0][tid], rmax[1][tid]),
                        fmaxf(rmax[2][tid], rmax[3][tid]));
        float S = expf(rmax[0][tid] - M) * rsum[0][tid]
                + expf(rmax[1][tid] - M) * rsum[1][tid]
                + expf(rmax[2][tid] - M) * rsum[2][tid]
                + expf(rmax[3][tid] - M) * rsum[3][tid];
        g_cmeta[(size_t)(b0 + tid) * NCCH + blockIdx.x] = make_float2(M, S);
    }
}

// ---------------------------------------------------------------------------
// K4: final combine — logsumexp over NCCH chunk stats, nll, mean.
// 1 block, 256 threads (one per b). Writes out directly (no atomics).
// ---------------------------------------------------------------------------
__global__ void k_ce2(float* __restrict__ out) {
    __shared__ float red[256];
    int b = threadIdx.x;
    float2 mt[NCCH];
#pragma unroll
    for (int i = 0; i < NCCH; i++) mt[i] = g_cmeta[(size_t)b * NCCH + i];
    float M = mt[0].x;
#pragma unroll
    for (int i = 1; i < NCCH; i++) M = fmaxf(M, mt[i].x);
    float den = 0.f;
#pragma unroll
    for (int i = 0; i < NCCH; i++) den = fmaf(expf(mt[i].x - M), mt[i].y, den);
    float nll = logf(den) + M - g_xg[b];

    red[b] = nll;
    __syncthreads();
#pragma unroll
    for (int s = 128; s; s >>= 1) {
        if (b < s) red[b] += red[b + s];
        __syncthreads();
    }
    if (b == 0) out[0] = red[0] * (1.0f / (float)Bq);
}

// ---------------------------------------------------------------------------
extern "C" void kernel_launch(void* const* d_in, const int* in_sizes, int n_in,
                              void* d_out, int out_size) {
    const float* toks         = (const float*)d_in[0];  // [B,N,D] f32
    const float* txt          = (const float*)d_in[1];  // [C,D]   f32
    const float* log_tau      = (const float*)d_in[2];  // scalar
    const float* log_attn_tau = (const float*)d_in[3];  // scalar
    const int*   gt           = (const int*)d_in[4];    // [B] int32
    float* out = (float*)d_out;

    dim3 gf(NCHUNK, Bq);
    k_fused<<<gf, 256>>>(toks, txt, gt, log_attn_tau);
    k_combine<<<Bq, 128>>>();
    dim3 gg(NCCH, Bq / 32);
    k_gemm_ce<<<gg, 256>>>(txt, log_tau, gt);
    k_ce2<<<1, 256>>>(out);
}

// round 15
// speedup vs baseline: 1.1202x; 1.0457x over previous
#include <cuda_runtime.h>
#include <math.h>
#include <stdint.h>

#define Bq 256
#define Nq 256
#define Dq 512
#define Cq 1024
#define NCHUNK 8
#define CH_ROWS (Nq / NCHUNK)   // 32 rows per fused block
#define NCCH 16                 // c-chunks in gemm (64 cols each)

// Scratch (device globals — no allocation allowed)
__device__ float  g_ppart[Bq * NCHUNK * Dq];       // partial weighted sums (4 MB)
__device__ float2 g_meta[Bq * NCHUNK];             // (m, den) per partial
__device__ float  g_pooled[Bq * Dq];               // pooled normalized tokens
__device__ float2 g_cmeta[Bq * NCCH];              // (max, sumexp) per (b, chunk)
__device__ float  g_xg[Bq];                        // logits[b][gt[b]] / tau

__device__ __forceinline__ float warp_sum1(float v) {
#pragma unroll
    for (int o = 16; o; o >>= 1) v += __shfl_xor_sync(0xffffffffu, v, o);
    return v;
}

__device__ __forceinline__ void warp_sum4(float& a, float& b, float& c, float& d) {
#pragma unroll
    for (int o = 16; o; o >>= 1) {
        a += __shfl_xor_sync(0xffffffffu, a, o);
        b += __shfl_xor_sync(0xffffffffu, b, o);
        c += __shfl_xor_sync(0xffffffffu, c, o);
        d += __shfl_xor_sync(0xffffffffu, d, o);
    }
}

__device__ __forceinline__ uint32_t f2tf32(float v) {
    uint32_t r;
    asm("cvt.rna.tf32.f32 %0, %1;" : "=r"(r) : "f"(v));
    return r;
}
__device__ __forceinline__ uint4 tf32x4(float4 v) {
    return make_uint4(f2tf32(v.x), f2tf32(v.y), f2tf32(v.z), f2tf32(v.w));
}

// ---------------------------------------------------------------------------
// K1 (fused streaming pass): online softmax-weighted pooling, single read of
// toks (128 MB). grid = (NCHUNK, B) = 2048 blocks, block = 256.
// ---------------------------------------------------------------------------
__global__ void k_fused(const float* __restrict__ toks,
                        const float* __restrict__ txt,
                        const int* __restrict__ gt,
                        const float* __restrict__ p_log_attn_tau) {
    __shared__ float sm[8], sden[8];
    __shared__ float svec[8][Dq];

    int ch = blockIdx.x, b = blockIdx.y;
    int w = threadIdx.x >> 5, lane = threadIdx.x & 31;

    float at = expf(*p_log_attn_tau);
    at = fminf(fmaxf(at, 0.01f), 1.0f);
    float inv_at = 1.f / at;

    int g = __ldg(&gt[b]);
    const float4* xrow = (const float4*)(txt + (size_t)g * Dq);
    float4 xv[4];
    float ssx = 0.f;
#pragma unroll
    for (int i = 0; i < 4; i++) {
        xv[i] = xrow[lane + 32 * i];
        ssx += xv[i].x * xv[i].x + xv[i].y * xv[i].y + xv[i].z * xv[i].z + xv[i].w * xv[i].w;
    }
    ssx = warp_sum1(ssx);
    float scale_x = inv_at / fmaxf(sqrtf(ssx), 1e-12f);

    int row0 = b * Nq + ch * CH_ROWS + w * 4;
    const float4* base = (const float4*)(toks + (size_t)row0 * Dq);

    float m = -1e30f, den = 0.f;
    float4 acc[4];
#pragma unroll
    for (int i = 0; i < 4; i++) acc[i] = make_float4(0.f, 0.f, 0.f, 0.f);

    float4 t0[4], t1[4], u0[4], u1[4];
#pragma unroll
    for (int i = 0; i < 4; i++) t0[i] = __ldcs(&base[lane + 32 * i]);
#pragma unroll
    for (int i = 0; i < 4; i++) t1[i] = __ldcs(&base[128 + lane + 32 * i]);

#pragma unroll
    for (int rp = 0; rp < 2; rp++) {
        if (rp == 0) {
#pragma unroll
            for (int i = 0; i < 4; i++) u0[i] = __ldcs(&base[256 + lane + 32 * i]);
#pragma unroll
            for (int i = 0; i < 4; i++) u1[i] = __ldcs(&base[384 + lane + 32 * i]);
        }
        float ss0 = 0.f, dp0 = 0.f, ss1 = 0.f, dp1 = 0.f;
#pragma unroll
        for (int i = 0; i < 4; i++) {
            ss0 += t0[i].x * t0[i].x + t0[i].y * t0[i].y + t0[i].z * t0[i].z + t0[i].w * t0[i].w;
            dp0 += t0[i].x * xv[i].x + t0[i].y * xv[i].y + t0[i].z * xv[i].z + t0[i].w * xv[i].w;
            ss1 += t1[i].x * t1[i].x + t1[i].y * t1[i].y + t1[i].z * t1[i].z + t1[i].w * t1[i].w;
            dp1 += t1[i].x * xv[i].x + t1[i].y * xv[i].y + t1[i].z * xv[i].z + t1[i].w * xv[i].w;
        }
        warp_sum4(ss0, dp0, ss1, dp1);

        float rn0 = 1.f / fmaxf(sqrtf(ss0), 1e-12f);
        float rn1 = 1.f / fmaxf(sqrtf(ss1), 1e-12f);
        float s0 = dp0 * rn0 * scale_x;
        float s1 = dp1 * rn1 * scale_x;
        float mnew = fmaxf(m, fmaxf(s0, s1));
        float scale = expf(m - mnew);
        float e0 = expf(s0 - mnew);
        float e1 = expf(s1 - mnew);
        den = den * scale + e0 + e1;
        float c0 = e0 * rn0, c1 = e1 * rn1;
#pragma unroll
        for (int i = 0; i < 4; i++) {
            acc[i].x = fmaf(c1, t1[i].x, fmaf(c0, t0[i].x, acc[i].x * scale));
            acc[i].y = fmaf(c1, t1[i].y, fmaf(c0, t0[i].y, acc[i].y * scale));
            acc[i].z = fmaf(c1, t1[i].z, fmaf(c0, t0[i].z, acc[i].z * scale));
            acc[i].w = fmaf(c1, t1[i].w, fmaf(c0, t0[i].w, acc[i].w * scale));
        }
        m = mnew;
        if (rp == 0) {
#pragma unroll
            for (int i = 0; i < 4; i++) { t0[i] = u0[i]; t1[i] = u1[i]; }
        }
    }

    if (lane == 0) { sm[w] = m; sden[w] = den; }
    float4* sv = (float4*)svec[w];
#pragma unroll
    for (int i = 0; i < 4; i++) sv[lane + 32 * i] = acc[i];
    __syncthreads();

    float M = sm[0];
#pragma unroll
    for (int i = 1; i < 8; i++) M = fmaxf(M, sm[i]);
    float wsc[8];
    float denb = 0.f;
#pragma unroll
    for (int i = 0; i < 8; i++) { wsc[i] = expf(sm[i] - M); denb = fmaf(wsc[i], sden[i], denb); }

    int tid = threadIdx.x;
    float* outp = g_ppart + (size_t)(b * NCHUNK + ch) * Dq;
#pragma unroll
    for (int rep = 0; rep < 2; rep++) {
        int d = tid + rep * 256;
        float v = 0.f;
#pragma unroll
        for (int i = 0; i < 8; i++) v = fmaf(wsc[i], svec[i][d], v);
        outp[d] = v;
    }
    if (tid == 0) g_meta[b * NCHUNK + ch] = make_float2(M, denb);
}

// ---------------------------------------------------------------------------
// K2: combine NCHUNK partials per b -> pooled[b,:]. grid = B, block = 128.
// Block 0 also zeroes out[0] for K4's atomicAdd (stream-ordered before K4).
// ---------------------------------------------------------------------------
__global__ void k_combine(float* __restrict__ out) {
    int b = blockIdx.x, tid = threadIdx.x;
    if (b == 0 && tid == 0) out[0] = 0.f;
    float2 mt[NCHUNK];
#pragma unroll
    for (int i = 0; i < NCHUNK; i++) mt[i] = g_meta[b * NCHUNK + i];
    float M = mt[0].x;
#pragma unroll
    for (int i = 1; i < NCHUNK; i++) M = fmaxf(M, mt[i].x);
    float den = 0.f;
    float sc[NCHUNK];
#pragma unroll
    for (int i = 0; i < NCHUNK; i++) { sc[i] = expf(mt[i].x - M); den = fmaf(sc[i], mt[i].y, den); }
    float inv_den = 1.f / den;

    const float4* part = (const float4*)(g_ppart + (size_t)b * NCHUNK * Dq);
    float4 acc = make_float4(0.f, 0.f, 0.f, 0.f);
#pragma unroll
    for (int i = 0; i < NCHUNK; i++) {
        float4 p = part[(size_t)i * (Dq / 4) + tid];
        acc.x = fmaf(sc[i], p.x, acc.x);
        acc.y = fmaf(sc[i], p.y, acc.y);
        acc.z = fmaf(sc[i], p.z, acc.z);
        acc.w = fmaf(sc[i], p.w, acc.w);
    }
    acc.x *= inv_den; acc.y *= inv_den; acc.z *= inv_den; acc.w *= inv_den;
    ((float4*)(g_pooled + (size_t)b * Dq))[tid] = acc;
}

// ---------------------------------------------------------------------------
// K3: fused GEMM + chunk-softmax-stats, smem double-buffered, full K=512
// (16 stages of 32). Tile 16b x 64c, block 256 = 8 warps, each warp m16n8
// over its own 8 columns. grid = (NCCH, B/16) = (16, 16) = 256 CTAs.
// Text read RAW; per-column 1/||txt_c|| accumulated from the same loads and
// applied in the epilogue.
// ---------------------------------------------------------------------------
__global__ void __launch_bounds__(256) k_gemm_ce(const float* __restrict__ txt,
                                                 const float* __restrict__ p_log_tau,
                                                 const int* __restrict__ gt) {
    __shared__ __align__(16) uint32_t As[2][16][36];
    __shared__ __align__(16) uint32_t Bs[2][64][36];
    __shared__ float rmax[8][16], rsum[8][16];
    __shared__ float srn[64];
    __shared__ int sgt[16];

    int tid = threadIdx.x;
    int c0 = blockIdx.x * 64;
    int b0 = blockIdx.y * 16;

    if (tid < 16) sgt[tid] = gt[b0 + tid];

    float tau = expf(*p_log_tau);
    tau = fminf(fmaxf(tau, 0.01f), 1.0f);
    float inv = 1.f / tau;

    int warp = tid >> 5, lane = tid & 31;   // warp = n-group (8 cols)
    int qg = lane >> 2, qt = lane & 3;

    // load assignments
    int rb = tid >> 3;             // 0..31  (B rows rb and rb+32)
    int cb = (tid & 7) * 4;        // 0..28
    int ra = tid >> 4;             // 0..15  (A rows, threads 0..255 -> rows 0..15 twice; use tid<128)
    int ca = (tid & 7) * 4;
    bool doA = tid < 128;          // 128 threads cover 16 rows x 32 cols /4

    const float* pA = &g_pooled[(size_t)(b0 + (tid >> 3 & 15)) * Dq + ca]; // rows 0..15 via (tid>>3)&15 for tid<128
    // simpler: for tid<128: rowA = tid>>3 (0..15), colA = (tid&7)*4
    int rowA = tid >> 3;           // valid when tid < 128 -> 0..15
    pA = &g_pooled[(size_t)(b0 + rowA) * Dq + ca];
    const float* pB0 = &txt[(size_t)(c0 + rb) * Dq + cb];
    const float* pB1 = &txt[(size_t)(c0 + rb + 32) * Dq + cb];

    float ssb0 = 0.f, ssb1 = 0.f;

    // prologue: stage-0 loads
    float4 a0 = doA ? *(const float4*)pA : make_float4(0.f, 0.f, 0.f, 0.f);
    float4 v0 = *(const float4*)pB0;
    float4 v1 = *(const float4*)pB1;

    float d0 = 0.f, d1 = 0.f, d2 = 0.f, d3 = 0.f;

#pragma unroll 1
    for (int stage = 0; stage < 16; stage++) {
        int buf = stage & 1;
        if (doA) *(uint4*)&As[buf][rowA][ca] = tf32x4(a0);
        *(uint4*)&Bs[buf][rb][cb]      = tf32x4(v0);
        *(uint4*)&Bs[buf][rb + 32][cb] = tf32x4(v1);
        ssb0 += v0.x * v0.x + v0.y * v0.y + v0.z * v0.z + v0.w * v0.w;
        ssb1 += v1.x * v1.x + v1.y * v1.y + v1.z * v1.z + v1.w * v1.w;
        __syncthreads();

        if (stage < 15) {   // prefetch next 32-k slab (hidden under MMA below)
            int o = (stage + 1) * 32;
            if (doA) a0 = *(const float4*)(pA + o);
            v0 = *(const float4*)(pB0 + o);
            v1 = *(const float4*)(pB1 + o);
        }

#pragma unroll
        for (int ks = 0; ks < 4; ks++) {
            int k = ks * 8;
            uint32_t af0 = As[buf][qg][k + qt];
            uint32_t af1 = As[buf][qg + 8][k + qt];
            uint32_t af2 = As[buf][qg][k + qt + 4];
            uint32_t af3 = As[buf][qg + 8][k + qt + 4];
            int n = warp * 8 + qg;
            uint32_t bf0 = Bs[buf][n][k + qt];
            uint32_t bf1 = Bs[buf][n][k + qt + 4];
            asm volatile(
                "mma.sync.aligned.m16n8k8.row.col.f32.tf32.tf32.f32 "
                "{%0,%1,%2,%3}, {%4,%5,%6,%7}, {%8,%9}, {%0,%1,%2,%3};"
                : "+f"(d0), "+f"(d1), "+f"(d2), "+f"(d3)
                : "r"(af0), "r"(af1), "r"(af2), "r"(af3), "r"(bf0), "r"(bf1));
        }
    }

    // ---- per-column reciprocal norms: reduce over the 8-lane (tid&7) group ----
#pragma unroll
    for (int o = 1; o < 8; o <<= 1) {
        ssb0 += __shfl_xor_sync(0xffffffffu, ssb0, o);
        ssb1 += __shfl_xor_sync(0xffffffffu, ssb1, o);
    }
    if ((tid & 7) == 0) {
        srn[rb]      = 1.f / fmaxf(sqrtf(ssb0), 1e-12f);
        srn[rb + 32] = 1.f / fmaxf(sqrtf(ssb1), 1e-12f);
    }
    __syncthreads();

    // ---- epilogue: scale by rn_c * inv_tau, chunk stats, gt extraction ----
    // thread covers rows qg, qg+8; cols warp*8 + 2qt, +1
    int ci0 = warp * 8 + 2 * qt;
    float s0c = srn[ci0] * inv;
    float s1c = srn[ci0 + 1] * inv;
    float va[2] = {d0 * s0c, d1 * s1c};       // row qg
    float vb[2] = {d2 * s0c, d3 * s1c};       // row qg+8

    int g0 = sgt[qg], g1 = sgt[qg + 8];
#pragma unroll
    for (int j = 0; j < 2; j++) {
        int col = c0 + ci0 + j;
        if (col == g0) g_xg[b0 + qg] = va[j];
        if (col == g1) g_xg[b0 + qg + 8] = vb[j];
    }

    // reduce max/sumexp over the 8 cols this warp owns for rows qg, qg+8
    float ma = fmaxf(va[0], va[1]);
    float mb = fmaxf(vb[0], vb[1]);
    ma = fmaxf(ma, __shfl_xor_sync(0xffffffffu, ma, 1));
    ma = fmaxf(ma, __shfl_xor_sync(0xffffffffu, ma, 2));
    mb = fmaxf(mb, __shfl_xor_sync(0xffffffffu, mb, 1));
    mb = fmaxf(mb, __shfl_xor_sync(0xffffffffu, mb, 2));
    float sa = expf(va[0] - ma) + expf(va[1] - ma);
    float sb = expf(vb[0] - mb) + expf(vb[1] - mb);
    sa += __shfl_xor_sync(0xffffffffu, sa, 1);
    sa += __shfl_xor_sync(0xffffffffu, sa, 2);
    sb += __shfl_xor_sync(0xffffffffu, sb, 1);
    sb += __shfl_xor_sync(0xffffffffu, sb, 2);
    if (qt == 0) {
        rmax[warp][qg] = ma;     rsum[warp][qg] = sa;
        rmax[warp][qg + 8] = mb; rsum[warp][qg + 8] = sb;
    }
    __syncthreads();

    if (tid < 16) {
        float M = rmax[0][tid];
#pragma unroll
        for (int i = 1; i < 8; i++) M = fmaxf(M, rmax[i][tid]);
        float S = 0.f;
#pragma unroll
        for (int i = 0; i < 8; i++) S = fmaf(expf(rmax[i][tid] - M), rsum[i][tid], S);
        g_cmeta[(size_t)(b0 + tid) * NCCH + blockIdx.x] = make_float2(M, S);
    }
}

// ---------------------------------------------------------------------------
// K4: final combine — logsumexp over NCCH chunk stats, nll, mean.
// grid = 8, block = 32: one b per thread; warp-reduce + atomicAdd.
// ---------------------------------------------------------------------------
__global__ void k_ce2(float* __restrict__ out) {
    int b = blockIdx.x * 32 + threadIdx.x;
    float2 mt[NCCH];
#pragma unroll
    for (int i = 0; i < NCCH; i++) mt[i] = g_cmeta[(size_t)b * NCCH + i];
    float M = mt[0].x;
#pragma unroll
    for (int i = 1; i < NCCH; i++) M = fmaxf(M, mt[i].x);
    float den = 0.f;
#pragma unroll
    for (int i = 0; i < NCCH; i++) den = fmaf(expf(mt[i].x - M), mt[i].y, den);
    float nll = logf(den) + M - g_xg[b];

    nll = warp_sum1(nll);
    if (threadIdx.x == 0) atomicAdd(out, nll * (1.0f / (float)Bq));
}

// ---------------------------------------------------------------------------
extern "C" void kernel_launch(void* const* d_in, const int* in_sizes, int n_in,
                              void* d_out, int out_size) {
    const float* toks         = (const float*)d_in[0];  // [B,N,D] f32
    const float* txt          = (const float*)d_in[1];  // [C,D]   f32
    const float* log_tau      = (const float*)d_in[2];  // scalar
    const float* log_attn_tau = (const float*)d_in[3];  // scalar
    const int*   gt           = (const int*)d_in[4];    // [B] int32
    float* out = (float*)d_out;

    dim3 gf(NCHUNK, Bq);
    k_fused<<<gf, 256>>>(toks, txt, gt, log_attn_tau);
    k_combine<<<Bq, 128>>>(out);
    dim3 gg(NCCH, Bq / 16);
    k_gemm_ce<<<gg, 256>>>(txt, log_tau, gt);
    k_ce2<<<8, 32>>>(out);
}